// round 1
// baseline (speedup 1.0000x reference)
#include <cuda_runtime.h>
#include <cstdint>

// Problem constants (fixed by setup_inputs): B=8, C=2, H=1080, W=1920
#define BB 8
#define HH 1080
#define WW 1920
#define HWV (HH * WW)          // 2,073,600
#define NN (BB * HWV)          // 16,588,800 cells

// Packed per-cell accumulator: (accx, accy, cnt, pad). 16B-aligned by construction.
// 265 MB static scratch — __device__ global (allocation-guard safe).
__device__ float4 g_acc[NN];

// -------------------------------------------------------------------------
// Scatter: one thread handles 4 consecutive pixels of one row (WW % 4 == 0).
// For each valid pixel, one red.global.add.v4.f32 per corner (4 total).
// -------------------------------------------------------------------------
__global__ __launch_bounds__(256) void flowproj_scatter(const float* __restrict__ flow) {
    int t = blockIdx.x * blockDim.x + threadIdx.x;
    int i0 = t * 4;
    if (i0 >= NN) return;

    int b = i0 / HWV;
    int r = i0 - b * HWV;
    int y = r / WW;
    int x = r - y * WW;

    const float* base = flow + (size_t)b * 2 * HWV + r;
    float4 fx4 = *reinterpret_cast<const float4*>(base);
    float4 fy4 = *reinterpret_cast<const float4*>(base + HWV);

    float fxs[4] = {fx4.x, fx4.y, fx4.z, fx4.w};
    float fys[4] = {fy4.x, fy4.y, fy4.z, fy4.w};

    float4* accb = g_acc + (size_t)b * HWV;
    float yf = (float)y;

#pragma unroll
    for (int k = 0; k < 4; k++) {
        float fx = fxs[k];
        float fy = fys[k];
        float x2 = (float)(x + k) + fx;
        float y2 = yf + fy;
        // valid per reference; invalid pixels contribute exact zeros -> skip
        if (x2 >= 0.0f && y2 >= 0.0f && x2 <= (float)(WW - 1) && y2 <= (float)(HH - 1)) {
            int xL = __float2int_rd(x2);
            int yT = __float2int_rd(y2);
            int xR = min(xL + 1, WW - 1);
            int yB = min(yT + 1, HH - 1);
            float vx = -fx;
            float vy = -fy;
            float4* pT = accb + yT * WW;
            float4* pB = accb + yB * WW;
            asm volatile("red.global.add.v4.f32 [%0], {%1,%2,%3,%4};"
                         :: "l"(pT + xL), "f"(vx), "f"(vy), "f"(1.0f), "f"(0.0f) : "memory");
            asm volatile("red.global.add.v4.f32 [%0], {%1,%2,%3,%4};"
                         :: "l"(pT + xR), "f"(vx), "f"(vy), "f"(1.0f), "f"(0.0f) : "memory");
            asm volatile("red.global.add.v4.f32 [%0], {%1,%2,%3,%4};"
                         :: "l"(pB + xL), "f"(vx), "f"(vy), "f"(1.0f), "f"(0.0f) : "memory");
            asm volatile("red.global.add.v4.f32 [%0], {%1,%2,%3,%4};"
                         :: "l"(pB + xR), "f"(vx), "f"(vy), "f"(1.0f), "f"(0.0f) : "memory");
        }
    }
}

// -------------------------------------------------------------------------
// Normalize: out[:,0] = accx/cnt, out[:,1] = accy/cnt (0 where cnt == 0).
// One thread handles 4 consecutive cells; HWV % 4 == 0 so all share b.
// -------------------------------------------------------------------------
__global__ __launch_bounds__(256) void flowproj_normalize(float* __restrict__ out) {
    int t = blockIdx.x * blockDim.x + threadIdx.x;
    int i0 = t * 4;
    if (i0 >= NN) return;

    int b = i0 / HWV;
    int r = i0 - b * HWV;

    float4 ox, oy;
    {
        float4 a0 = g_acc[i0 + 0];
        float4 a1 = g_acc[i0 + 1];
        float4 a2 = g_acc[i0 + 2];
        float4 a3 = g_acc[i0 + 3];
        float i0v = (a0.z > 0.0f) ? (1.0f / a0.z) : 0.0f;
        float i1v = (a1.z > 0.0f) ? (1.0f / a1.z) : 0.0f;
        float i2v = (a2.z > 0.0f) ? (1.0f / a2.z) : 0.0f;
        float i3v = (a3.z > 0.0f) ? (1.0f / a3.z) : 0.0f;
        ox = make_float4(a0.x * i0v, a1.x * i1v, a2.x * i2v, a3.x * i3v);
        oy = make_float4(a0.y * i0v, a1.y * i1v, a2.y * i2v, a3.y * i3v);
    }

    float* po = out + (size_t)b * 2 * HWV + r;
    *reinterpret_cast<float4*>(po) = ox;
    *reinterpret_cast<float4*>(po + HWV) = oy;
}

extern "C" void kernel_launch(void* const* d_in, const int* in_sizes, int n_in,
                              void* d_out, int out_size) {
    (void)in_sizes; (void)n_in; (void)out_size;
    const float* flow = (const float*)d_in[0];
    float* out = (float*)d_out;

    void* acc_ptr = nullptr;
    cudaGetSymbolAddress(&acc_ptr, g_acc);

    // 1) zero accumulators (memset node in the graph)
    cudaMemsetAsync(acc_ptr, 0, (size_t)NN * sizeof(float4));

    // 2) scatter
    {
        int threads = NN / 4;            // 4,147,200
        int block = 256;
        int grid = (threads + block - 1) / block;
        flowproj_scatter<<<grid, block>>>(flow);
    }

    // 3) normalize
    {
        int threads = NN / 4;
        int block = 256;
        int grid = (threads + block - 1) / block;
        flowproj_normalize<<<grid, block>>>(out);
    }
}